// round 16
// baseline (speedup 1.0000x reference)
#include <cuda_runtime.h>
#include <cuda_fp16.h>
#include <cstdint>
#include <cstddef>

#define NN 50000
#define EE 1600000
#define MTILES ((NN + 63) / 64)   // 782
#define ETILES (EE / 128)         // 12500 (exact)
#define PBLOCKS 296               // 2 per SM

// ---------------- scratch (static device globals; no dynamic alloc) ----------
__device__ __align__(16) __half g_n1h[(size_t)NN * 64];
__device__ __align__(16) __half g_Ph[(size_t)NN * 128];
__device__ __align__(16) float  g_Bn[(size_t)NN * 128];
__device__ __align__(16) float  g_AGG[(size_t)NN * 64];
__device__ __align__(16) float  g_ssum[2 * NN];            // interleaved {spos, sneg}
__device__ __align__(16) float g_cpos[128];
__device__ __align__(16) float g_cneg[128];
__device__ __align__(16) float g_apos[128];
__device__ __align__(16) float g_aneg[128];
__device__ float  g_wpos[64], g_wneg[64];
__device__ __align__(16) uint4 g_CB[64];
__device__ __align__(16) __half g_Wcombh[256 * 64];
__device__ __align__(16) __half g_We1h[64 * 128];
__device__ __align__(16) __half g_Wn1h[64 * 128];
__device__ __align__(16) __half g_Wfn1h[128 * 128];

// ---------------- helpers ----------------------------------------------------
__device__ __forceinline__ void red_add_v4(float* p, float4 v) {
    asm volatile("red.global.add.v4.f32 [%0], {%1,%2,%3,%4};"
                 :: "l"(p), "f"(v.x), "f"(v.y), "f"(v.z), "f"(v.w) : "memory");
}
__device__ __forceinline__ void red_add_v2(float* p, float2 v) {
    asm volatile("red.global.add.v2.f32 [%0], {%1,%2};"
                 :: "l"(p), "f"(v.x), "f"(v.y) : "memory");
}
__device__ __forceinline__ uint32_t smem_u32(const void* p) {
    uint32_t a;
    asm("{ .reg .u64 t; cvta.to.shared.u64 t, %1; cvt.u32.u64 %0, t; }" : "=r"(a) : "l"(p));
    return a;
}

// ---------------- zero scratch (vectorized) -----------------------------------
__global__ void kzero() {
    int t = blockIdx.x * blockDim.x + threadIdx.x;
    float4 z = make_float4(0.f, 0.f, 0.f, 0.f);
    if (t < NN * 16) ((float4*)g_AGG)[t] = z;
    else if (t < NN * 16 + NN / 2) ((float4*)g_ssum)[t - NN * 16] = z;
}

// ---------------- K0: fold rank-1 edge path + fp16 weight conversions --------
__global__ void k0(const float* __restrict__ We0, const float* __restrict__ Wfe0,
                   const float* __restrict__ Wfn0, const float* __restrict__ We1,
                   const float* __restrict__ Wn1, const float* __restrict__ Wfn1,
                   const float* __restrict__ bfe0) {
    int t = threadIdx.x;
    if (t < 64) {
        float w = We0[t];
        g_wpos[t] = fmaxf(w, 0.f);
        g_wneg[t] = fminf(w, 0.f);
    }
    __syncthreads();
    if (t < 128) {
        float cp = 0.f, cn = 0.f, ap = 0.f, an = 0.f;
        for (int j = 0; j < 64; j++) {
            float wp = g_wpos[j], wn = g_wneg[j];
            float we = Wfe0[t * 128 + 64 + j];
            float wf = Wfn0[t * 128 + j];
            cp += wp * we; cn += wn * we;
            ap += wp * wf; an += wn * wf;
        }
        g_cpos[t] = cp; g_cneg[t] = cn; g_apos[t] = ap; g_aneg[t] = an;
    }
    __syncthreads();
    if (t < 64) {
        uint4 cb;
        __half2* h = (__half2*)&cb;
        h[0] = __floats2half2_rn(g_cpos[2 * t], g_cpos[2 * t + 1]);
        h[1] = __floats2half2_rn(g_cneg[2 * t], g_cneg[2 * t + 1]);
        h[2] = __floats2half2_rn(bfe0[2 * t], bfe0[2 * t + 1]);
        h[3] = __floats2half2_rn(0.f, 0.f);
        g_CB[t] = cb;
    }
    for (int idx = t; idx < 256 * 64; idx += blockDim.x) {
        int r = idx >> 6, j = idx & 63;
        float v = (r < 128) ? Wfe0[r * 128 + j] : Wfn0[(r - 128) * 128 + 64 + j];
        g_Wcombh[idx] = __float2half(v);
    }
    for (int idx = t; idx < 64 * 128; idx += blockDim.x) {
        g_We1h[idx] = __float2half(We1[idx]);
        g_Wn1h[idx] = __float2half(Wn1[idx]);
    }
    for (int idx = t; idx < 128 * 128; idx += blockDim.x)
        g_Wfn1h[idx] = __float2half(Wfn1[idx]);
}

// ---------------- K1: n1h = relu(x @ Wn0^T) fp16 ------------------------------
__global__ void k1(const float* __restrict__ x, const float* __restrict__ Wn0) {
    int t = blockIdx.x * blockDim.x + threadIdx.x;
    if (t >= NN * 64) return;
    int n = t >> 6, j = t & 63;
    const float* xr = x + (size_t)n * 16;
    const float* wr = Wn0 + j * 16;
    float s = 0.f;
#pragma unroll
    for (int k = 0; k < 16; k++) s += xr[k] * __ldg(wr + k);
    g_n1h[t] = __float2half(fmaxf(s, 0.f));
}

// ---------------- gemm01: HMMA [M,64] @ Wcombh[256,64]^T ----------------------
__global__ __launch_bounds__(256) void gemm01(int M) {
    extern __shared__ char smc[];
    const uint32_t uA = smem_u32(smc);
    const uint32_t uB = uA + 8192;
    int t = threadIdx.x;
    int m0 = blockIdx.x * 64;
    const __half* Bt = g_Wcombh + (size_t)(blockIdx.y * 64) * 64;

#pragma unroll
    for (int ii = 0; ii < 2; ii++) {
        int seg = t + (ii << 8);
        int row = seg >> 3, cs = seg & 7;
        uint4 v = make_uint4(0, 0, 0, 0);
        if (m0 + row < M) v = *((const uint4*)(g_n1h + (size_t)(m0 + row) * 64) + cs);
        int cb = (cs << 4) ^ ((row & 7) << 4);
        *(uint4*)(smc + row * 128 + cb) = v;
    }
#pragma unroll
    for (int ii = 0; ii < 2; ii++) {
        int seg = t + (ii << 8);
        int row = seg >> 3, cs = seg & 7;
        uint4 v = *((const uint4*)(Bt + row * 64) + cs);
        int cb = (cs << 4) ^ ((row & 7) << 4);
        *(uint4*)(smc + 8192 + row * 128 + cb) = v;
    }
    __syncthreads();

    int lane = t & 31, w = t >> 5;
    int mw = (w & 3) << 4;
    int nw = w >> 2;
    int selA = lane >> 3, rA = lane & 7;
    int arow = mw + rA + ((selA & 1) << 3);
    int acb0 = (selA >> 1) << 4;
    int ax = (arow & 7) << 4;
    uint32_t aRowBase = uA + arow * 128;
    int selB = (lane >> 3) & 1, rB = lane & 7;
    int bx = rB << 4;

    float acc[4][4];
#pragma unroll
    for (int j = 0; j < 4; j++)
#pragma unroll
        for (int i = 0; i < 4; i++) acc[j][i] = 0.f;

#pragma unroll
    for (int k = 0; k < 4; k++) {
        uint32_t a0, a1, a2, a3;
        uint32_t aAddr = aRowBase + (((k << 5) + acb0) ^ ax);
        asm volatile("ldmatrix.sync.aligned.m8n8.x4.shared.b16 {%0,%1,%2,%3}, [%4];"
                     : "=r"(a0), "=r"(a1), "=r"(a2), "=r"(a3) : "r"(aAddr));
#pragma unroll
        for (int j = 0; j < 4; j++) {
            int brow = (nw << 5) + (j << 3) + rB;
            uint32_t bAddr = uB + brow * 128 + (((k << 5) + (selB << 4)) ^ bx);
            uint32_t b0, b1;
            asm volatile("ldmatrix.sync.aligned.m8n8.x2.shared.b16 {%0,%1}, [%2];"
                         : "=r"(b0), "=r"(b1) : "r"(bAddr));
            asm volatile("mma.sync.aligned.m16n8k16.row.col.f32.f16.f16.f32 "
                         "{%0,%1,%2,%3}, {%4,%5,%6,%7}, {%8,%9}, {%0,%1,%2,%3};"
                         : "+f"(acc[j][0]), "+f"(acc[j][1]), "+f"(acc[j][2]), "+f"(acc[j][3])
                         : "r"(a0), "r"(a1), "r"(a2), "r"(a3), "r"(b0), "r"(b1));
        }
    }

    int col = (nw << 5) + ((lane & 3) << 1);
    int row0 = mw + (lane >> 2);
    int gcol = blockIdx.y * 64;
#pragma unroll
    for (int j = 0; j < 4; j++) {
        int c = col + (j << 3);
#pragma unroll
        for (int h = 0; h < 2; h++) {
            int m = m0 + row0 + h * 8;
            if (m >= M) continue;
            float v0 = acc[j][h * 2], v1 = acc[j][h * 2 + 1];
            if (gcol < 128) {
                *(__half2*)(g_Ph + (size_t)m * 128 + gcol + c) = __floats2half2_rn(v0, v1);
            } else {
                *(float2*)(g_Bn + (size_t)m * 128 + (gcol - 128) + c) = make_float2(v0, v1);
            }
        }
    }
}

// ---------------- persistent pipelined edge kernel ----------------------------
struct EdgeRegs {
    uint4 vs1[4], vd1[4], vs2[4], vd2[4];
    int dst1, dst2;
    float a1, a2;
};

__device__ __forceinline__ void fetch_tile(
    int tile, int erow, int q, const int* __restrict__ ei,
    const float* __restrict__ ea, EdgeRegs& r, int* sDstBuf) {
    int e0 = tile << 7;
    int e1i = e0 + erow;
    int e2i = e0 + erow + 64;
    int src1 = ei[e1i]; r.dst1 = ei[EE + e1i]; r.a1 = ea[e1i];
    int src2 = ei[e2i]; r.dst2 = ei[EE + e2i]; r.a2 = ea[e2i];
    const uint4* Ps1 = (const uint4*)(g_Ph + (size_t)src1 * 128);
    const uint4* Pd1 = (const uint4*)(g_Ph + (size_t)r.dst1 * 128);
    const uint4* Ps2 = (const uint4*)(g_Ph + (size_t)src2 * 128);
    const uint4* Pd2 = (const uint4*)(g_Ph + (size_t)r.dst2 * 128);
#pragma unroll
    for (int s = 0; s < 4; s++) {
        int seg = s * 4 + q;
        r.vs1[s] = __ldg(Ps1 + seg);
        r.vd1[s] = __ldg(Pd1 + seg);
        r.vs2[s] = __ldg(Ps2 + seg);
        r.vd2[s] = __ldg(Pd2 + seg);
    }
    if (q == 0) {
        sDstBuf[erow] = r.dst1;
        sDstBuf[erow + 64] = r.dst2;
        red_add_v2(g_ssum + 2 * r.dst1, make_float2(fmaxf(r.a1, 0.f), fminf(r.a1, 0.f)));
        red_add_v2(g_ssum + 2 * r.dst2, make_float2(fmaxf(r.a2, 0.f), fminf(r.a2, 0.f)));
    }
}

__device__ __forceinline__ void build_tile(
    const EdgeRegs& r, int erow, int q, char* smc, uint32_t bufOff,
    const uint4* sCB) {
    const __half2 z2 = __floats2half2_rn(0.f, 0.f);
    const int erow2 = erow + 64;
    const int xr1 = (erow & 7) << 4;
    const int xr2 = (erow2 & 7) << 4;
    __half2 ap1 = __float2half2_rn(fmaxf(r.a1, 0.f));
    __half2 an1 = __float2half2_rn(fminf(r.a1, 0.f));
    __half2 ap2 = __float2half2_rn(fmaxf(r.a2, 0.f));
    __half2 an2 = __float2half2_rn(fminf(r.a2, 0.f));
#pragma unroll
    for (int s = 0; s < 4; s++) {
        int hc = (s << 5) + (q << 3);
        uint4 cbv[4];
#pragma unroll
        for (int p = 0; p < 4; p++) cbv[p] = sCB[(hc >> 1) + p];

        const __half2* hs1 = (const __half2*)&r.vs1[s];
        const __half2* hd1 = (const __half2*)&r.vd1[s];
        const __half2* hs2 = (const __half2*)&r.vs2[s];
        const __half2* hd2 = (const __half2*)&r.vd2[s];
        uint4 out1, out2;
        __half2* ho1 = (__half2*)&out1;
        __half2* ho2 = (__half2*)&out2;
#pragma unroll
        for (int p = 0; p < 4; p++) {
            const __half2* hcb = (const __half2*)&cbv[p];
            __half2 t1 = __hfma2(ap1, hcb[0], __hfma2(an1, hcb[1], hcb[2]));
            __half2 t2 = __hfma2(ap2, hcb[0], __hfma2(an2, hcb[1], hcb[2]));
            ho1[p] = __hmax2(__hadd2(__hadd2(hs1[p], hd1[p]), t1), z2);
            ho2[p] = __hmax2(__hadd2(__hadd2(hs2[p], hd2[p]), t2), z2);
        }
        *(uint4*)(smc + bufOff + erow * 256 + ((hc << 1) ^ xr1)) = out1;
        *(uint4*)(smc + bufOff + erow2 * 256 + ((hc << 1) ^ xr2)) = out2;
    }
}

__global__ __launch_bounds__(256, 2) void edge_kernel(
    const int* __restrict__ ei, const float* __restrict__ ea) {
    extern __shared__ char smc[];
    // U0 [0,32768), U1 [32768,65536), W [65536,81920)
    __shared__ int   sDst[2][128];
    __shared__ uint4 sCB[64];

    const uint32_t uU = smem_u32(smc);
    const uint32_t uW = uU + 65536;

    int t = threadIdx.x;
    const int erow = t >> 2;
    const int q = t & 3;

    if (t < 64) sCB[t] = g_CB[t];
#pragma unroll
    for (int ii = 0; ii < 4; ii++) {
        int seg = t + (ii << 8);
        int row = seg >> 4, cs = seg & 15;
        uint4 v = *((const uint4*)(g_We1h + row * 128) + cs);
        int cb = (cs << 4) ^ ((row & 7) << 4);
        *(uint4*)(smc + 65536 + row * 256 + cb) = v;
    }

    int lane = t & 31, w = t >> 5;
    int mw = (w & 3) << 5;
    int nw = w >> 2;
    int selA = lane >> 3, rA = lane & 7;
    int acb0 = (selA >> 1) << 4;
    int rowOff = rA + ((selA & 1) << 3);
    int selB = (lane >> 3) & 1, rB = lane & 7;
    int bx = rB << 4;
    int qe = lane & 3, qodd = qe & 1;
    int colb = (nw << 5) + ((qe >> 1) << 2);

    int tile = blockIdx.x;
    EdgeRegs reg;
    fetch_tile(tile, erow, q, ei, ea, reg, sDst[0]);
    __syncthreads();
    build_tile(reg, erow, q, smc, 0, sCB);
    __syncthreads();

    int buf = 0;
    while (true) {
        int next = tile + PBLOCKS;
        bool have_next = (next < ETILES);
        if (have_next)
            fetch_tile(next, erow, q, ei, ea, reg, sDst[buf ^ 1]);

        uint32_t uBuf = uU + ((uint32_t)buf << 15);
        float acc[2][4][4];
#pragma unroll
        for (int mi = 0; mi < 2; mi++)
#pragma unroll
            for (int j = 0; j < 4; j++)
#pragma unroll
                for (int i = 0; i < 4; i++) acc[mi][j][i] = 0.f;

#pragma unroll
        for (int k = 0; k < 8; k++) {
            uint32_t a[2][4];
#pragma unroll
            for (int mi = 0; mi < 2; mi++) {
                int arow = mw + (mi << 4) + rowOff;
                uint32_t aAddr = uBuf + arow * 256 + (((k << 5) + acb0) ^ ((arow & 7) << 4));
                asm volatile("ldmatrix.sync.aligned.m8n8.x4.shared.b16 {%0,%1,%2,%3}, [%4];"
                             : "=r"(a[mi][0]), "=r"(a[mi][1]), "=r"(a[mi][2]), "=r"(a[mi][3])
                             : "r"(aAddr));
            }
#pragma unroll
            for (int j = 0; j < 4; j++) {
                int brow = (nw << 5) + (j << 3) + rB;
                uint32_t bAddr = uW + brow * 256 + (((k << 5) + (selB << 4)) ^ bx);
                uint32_t b0, b1;
                asm volatile("ldmatrix.sync.aligned.m8n8.x2.shared.b16 {%0,%1}, [%2];"
                             : "=r"(b0), "=r"(b1) : "r"(bAddr));
#pragma unroll
                for (int mi = 0; mi < 2; mi++) {
                    asm volatile("mma.sync.aligned.m16n8k16.row.col.f32.f16.f16.f32 "
                                 "{%0,%1,%2,%3}, {%4,%5,%6,%7}, {%8,%9}, {%0,%1,%2,%3};"
                                 : "+f"(acc[mi][j][0]), "+f"(acc[mi][j][1]),
                                   "+f"(acc[mi][j][2]), "+f"(acc[mi][j][3])
                                 : "r"(a[mi][0]), "r"(a[mi][1]), "r"(a[mi][2]), "r"(a[mi][3]),
                                   "r"(b0), "r"(b1));
                }
            }
        }

#pragma unroll
        for (int mi = 0; mi < 2; mi++) {
            int row0 = mw + (mi << 4) + (lane >> 2);
#pragma unroll
            for (int j = 0; j < 4; j++)
#pragma unroll
                for (int c = 0; c < 4; c++) acc[mi][j][c] = fmaxf(acc[mi][j][c], 0.f);
#pragma unroll
            for (int j = 0; j < 4; j++) {
                float s0 = __shfl_xor_sync(0xffffffffu,
                                           qodd ? acc[mi][j][0] : acc[mi][j][2], 1);
                float s1 = __shfl_xor_sync(0xffffffffu,
                                           qodd ? acc[mi][j][1] : acc[mi][j][3], 1);
                int row = qodd ? (row0 + 8) : row0;
                int d = sDst[buf][row];
                float4 v = qodd ? make_float4(s0, s1, acc[mi][j][2], acc[mi][j][3])
                                : make_float4(acc[mi][j][0], acc[mi][j][1], s0, s1);
                red_add_v4(g_AGG + (size_t)d * 64 + colb + (j << 3), v);
            }
        }

        if (!have_next) break;
        build_tile(reg, erow, q, smc, (uint32_t)(buf ^ 1) << 15, sCB);
        __syncthreads();
        buf ^= 1;
        tile = next;
    }
}

// ---------------- node1: fused layer-1 node megakernel ------------------------
// Per 64-row tile: X = BN0(relu(ssum-part + Bn + bfn0)) -> smem fp16;
// MMA1 n1_1 = X @ Wn1^T -> smem A cols 64..127 (A cols 0..63 = fp16(agg1));
// reload W2=Wfn1 over X/Wn1; MMA2 out = A @ W2^T with bias+relu+BN1 -> f32.
// smem: A [0,32768) ; X [32768,49152) ; Wn1 [49152,65536) ; W2 over [32768,65536)
__global__ __launch_bounds__(256) void node1(
    const float* __restrict__ bfn0, const float* __restrict__ g0,
    const float* __restrict__ b0, const float* __restrict__ rm0,
    const float* __restrict__ rv0, const float* __restrict__ bfn1,
    const float* __restrict__ g1, const float* __restrict__ b1,
    const float* __restrict__ rm1, const float* __restrict__ rv1,
    float* __restrict__ out) {
    extern __shared__ char smc[];
    const uint32_t uA = smem_u32(smc);
    const uint32_t uX = uA + 32768;
    const uint32_t uW1 = uA + 49152;
    const uint32_t uW2 = uA + 32768;
    int t = threadIdx.x;
    int m0 = blockIdx.x * 64;
    int lane = t & 31, w = t >> 5;

    // Wn1 -> smem swizzled (1024 segs)
#pragma unroll
    for (int ii = 0; ii < 4; ii++) {
        int seg = t + (ii << 8);
        int row = seg >> 4, cs = seg & 15;
        uint4 v = *((const uint4*)(g_Wn1h + row * 128) + cs);
        *(uint4*)(smc + 49152 + row * 256 + ((cs << 4) ^ ((row & 7) << 4))) = v;
    }

    // X tile (BN0 epilogue) + A-left (fp16 agg1)
    {
        int row = t >> 2, q = t & 3;
        int m = m0 + row;
        bool ok = (m < NN);
        float sp = ok ? g_ssum[2 * m] : 0.f;
        float sn = ok ? g_ssum[2 * m + 1] : 0.f;
        int xr = (row & 7) << 4;
#pragma unroll
        for (int s = 0; s < 4; s++) {
            int hc = (q << 5) + (s << 3);
            uint4 outv;
            __half2* ho = (__half2*)&outv;
#pragma unroll
            for (int pp = 0; pp < 2; pp++) {
                int c = hc + pp * 4;
                float4 bn = ok ? *(const float4*)(g_Bn + (size_t)m * 128 + c)
                               : make_float4(0.f, 0.f, 0.f, 0.f);
                float4 ap = *(const float4*)(g_apos + c);
                float4 an = *(const float4*)(g_aneg + c);
                float4 bf = *(const float4*)(bfn0 + c);
                float4 rm = *(const float4*)(rm0 + c);
                float4 rv = *(const float4*)(rv0 + c);
                float4 gg = *(const float4*)(g0 + c);
                float4 bb = *(const float4*)(b0 + c);
                float v0 = fmaxf(sp * ap.x + sn * an.x + bn.x + bf.x, 0.f);
                float v1 = fmaxf(sp * ap.y + sn * an.y + bn.y + bf.y, 0.f);
                float v2 = fmaxf(sp * ap.z + sn * an.z + bn.z + bf.z, 0.f);
                float v3 = fmaxf(sp * ap.w + sn * an.w + bn.w + bf.w, 0.f);
                v0 = (v0 - rm.x) * rsqrtf(rv.x + 1e-5f) * gg.x + bb.x;
                v1 = (v1 - rm.y) * rsqrtf(rv.y + 1e-5f) * gg.y + bb.y;
                v2 = (v2 - rm.z) * rsqrtf(rv.z + 1e-5f) * gg.z + bb.z;
                v3 = (v3 - rm.w) * rsqrtf(rv.w + 1e-5f) * gg.w + bb.w;
                ho[pp * 2]     = __floats2half2_rn(v0, v1);
                ho[pp * 2 + 1] = __floats2half2_rn(v2, v3);
            }
            *(uint4*)(smc + 32768 + row * 256 + ((hc << 1) ^ xr)) = outv;
        }
#pragma unroll
        for (int s = 0; s < 2; s++) {
            int hc = (q << 4) + (s << 3);
            float4 a0 = ok ? *(const float4*)(g_AGG + (size_t)m * 64 + hc)
                           : make_float4(0.f, 0.f, 0.f, 0.f);
            float4 a1 = ok ? *(const float4*)(g_AGG + (size_t)m * 64 + hc + 4)
                           : make_float4(0.f, 0.f, 0.f, 0.f);
            uint4 outv;
            __half2* ho = (__half2*)&outv;
            ho[0] = __floats2half2_rn(a0.x, a0.y);
            ho[1] = __floats2half2_rn(a0.z, a0.w);
            ho[2] = __floats2half2_rn(a1.x, a1.y);
            ho[3] = __floats2half2_rn(a1.z, a1.w);
            *(uint4*)(smc + row * 256 + ((hc << 1) ^ xr)) = outv;
        }
    }
    __syncthreads();

    // common MMA coordinates
    int mw = (w & 3) << 4;
    int nw = w >> 2;
    int selA = lane >> 3, rA = lane & 7;
    int arow = mw + rA + ((selA & 1) << 3);
    int acb0 = (selA >> 1) << 4;
    int ax = (arow & 7) << 4;
    int selB = (lane >> 3) & 1, rB = lane & 7;
    int bx = rB << 4;

    // ---- MMA1: n1_1 = X @ Wn1^T [64x64] -> A cols 64..127 (fp16) ----
    {
        float acc[4][4];
#pragma unroll
        for (int j = 0; j < 4; j++)
#pragma unroll
            for (int i = 0; i < 4; i++) acc[j][i] = 0.f;
#pragma unroll
        for (int k = 0; k < 8; k++) {
            uint32_t a0, a1, a2, a3;
            uint32_t aAddr = uX + arow * 256 + (((k << 5) + acb0) ^ ax);
            asm volatile("ldmatrix.sync.aligned.m8n8.x4.shared.b16 {%0,%1,%2,%3}, [%4];"
                         : "=r"(a0), "=r"(a1), "=r"(a2), "=r"(a3) : "r"(aAddr));
#pragma unroll
            for (int j = 0; j < 4; j++) {
                int brow = (nw << 5) + (j << 3) + rB;
                uint32_t bAddr = uW1 + brow * 256 + (((k << 5) + (selB << 4)) ^ bx);
                uint32_t b0, b1;
                asm volatile("ldmatrix.sync.aligned.m8n8.x2.shared.b16 {%0,%1}, [%2];"
                             : "=r"(b0), "=r"(b1) : "r"(bAddr));
                asm volatile("mma.sync.aligned.m16n8k16.row.col.f32.f16.f16.f32 "
                             "{%0,%1,%2,%3}, {%4,%5,%6,%7}, {%8,%9}, {%0,%1,%2,%3};"
                             : "+f"(acc[j][0]), "+f"(acc[j][1]), "+f"(acc[j][2]), "+f"(acc[j][3])
                             : "r"(a0), "r"(a1), "r"(a2), "r"(a3), "r"(b0), "r"(b1));
            }
        }
        int col = (nw << 5) + ((lane & 3) << 1);
        int row0 = mw + (lane >> 2);
#pragma unroll
        for (int j = 0; j < 4; j++) {
            int hcol = 64 + col + (j << 3);
#pragma unroll
            for (int h = 0; h < 2; h++) {
                int row = row0 + h * 8;
                float v0 = fmaxf(acc[j][h * 2], 0.f);
                float v1 = fmaxf(acc[j][h * 2 + 1], 0.f);
                int off = (hcol << 1) ^ ((row & 7) << 4);
                *(__half2*)(smc + row * 256 + off) = __floats2half2_rn(v0, v1);
            }
        }
    }
    __syncthreads();

    // ---- W2 = Wfn1 over X/Wn1 region (2048 segs) ----
#pragma unroll
    for (int ii = 0; ii < 8; ii++) {
        int seg = t + (ii << 8);
        int row = seg >> 4, cs = seg & 15;
        uint4 v = *((const uint4*)(g_Wfn1h + row * 128) + cs);
        *(uint4*)(smc + 32768 + row * 256 + ((cs << 4) ^ ((row & 7) << 4))) = v;
    }
    __syncthreads();

    // ---- MMA2: out = A @ W2^T [64x128], BN1 epilogue ----
    {
        float acc[8][4];
#pragma unroll
        for (int j = 0; j < 8; j++)
#pragma unroll
            for (int i = 0; i < 4; i++) acc[j][i] = 0.f;
#pragma unroll
        for (int k = 0; k < 8; k++) {
            uint32_t a0, a1, a2, a3;
            uint32_t aAddr = uA + arow * 256 + (((k << 5) + acb0) ^ ax);
            asm volatile("ldmatrix.sync.aligned.m8n8.x4.shared.b16 {%0,%1,%2,%3}, [%4];"
                         : "=r"(a0), "=r"(a1), "=r"(a2), "=r"(a3) : "r"(aAddr));
#pragma unroll
            for (int j = 0; j < 8; j++) {
                int brow = (nw << 6) + (j << 3) + rB;
                uint32_t bAddr = uW2 + brow * 256 + (((k << 5) + (selB << 4)) ^ bx);
                uint32_t b0, b1;
                asm volatile("ldmatrix.sync.aligned.m8n8.x2.shared.b16 {%0,%1}, [%2];"
                             : "=r"(b0), "=r"(b1) : "r"(bAddr));
                asm volatile("mma.sync.aligned.m16n8k16.row.col.f32.f16.f16.f32 "
                             "{%0,%1,%2,%3}, {%4,%5,%6,%7}, {%8,%9}, {%0,%1,%2,%3};"
                             : "+f"(acc[j][0]), "+f"(acc[j][1]), "+f"(acc[j][2]), "+f"(acc[j][3])
                             : "r"(a0), "r"(a1), "r"(a2), "r"(a3), "r"(b0), "r"(b1));
            }
        }
        int col = (nw << 6) + ((lane & 3) << 1);
        int row0 = mw + (lane >> 2);
#pragma unroll
        for (int j = 0; j < 8; j++) {
            int gc = col + (j << 3);
#pragma unroll
            for (int h = 0; h < 2; h++) {
                int m = m0 + row0 + h * 8;
                if (m >= NN) continue;
                float v0 = acc[j][h * 2] + bfn1[gc];
                float v1 = acc[j][h * 2 + 1] + bfn1[gc + 1];
                v0 = fmaxf(v0, 0.f); v1 = fmaxf(v1, 0.f);
                v0 = (v0 - rm1[gc]) * rsqrtf(rv1[gc] + 1e-5f) * g1[gc] + b1[gc];
                v1 = (v1 - rm1[gc + 1]) * rsqrtf(rv1[gc + 1] + 1e-5f) * g1[gc + 1] + b1[gc + 1];
                *(float2*)(out + (size_t)m * 128 + gc) = make_float2(v0, v1);
            }
        }
    }
}

// ---------------- host launcher ----------------------------------------------
extern "C" void kernel_launch(void* const* d_in, const int* in_sizes, int n_in,
                              void* d_out, int out_size) {
    const float* x    = (const float*)d_in[0];
    const float* ea   = (const float*)d_in[1];
    const int*   ei   = (const int*)d_in[2];
    const float* Wn0  = (const float*)d_in[3];
    const float* We0  = (const float*)d_in[4];
    const float* Wfn0 = (const float*)d_in[5];
    const float* bfn0 = (const float*)d_in[6];
    const float* Wfe0 = (const float*)d_in[7];
    const float* bfe0 = (const float*)d_in[8];
    const float* g0   = (const float*)d_in[9];
    const float* b0   = (const float*)d_in[10];
    const float* rm0  = (const float*)d_in[11];
    const float* rv0  = (const float*)d_in[12];
    const float* Wn1  = (const float*)d_in[13];
    const float* We1  = (const float*)d_in[14];
    const float* Wfn1 = (const float*)d_in[15];
    const float* bfn1 = (const float*)d_in[16];
    const float* g1   = (const float*)d_in[19];
    const float* b1   = (const float*)d_in[20];
    const float* rm1  = (const float*)d_in[21];
    const float* rv1  = (const float*)d_in[22];

    const int SMG = 16384;   // gemm01
    const int SME = 81920;   // edge kernel
    const int SMN = 65536;   // node1
    cudaFuncSetAttribute(edge_kernel, cudaFuncAttributeMaxDynamicSharedMemorySize, SME);
    cudaFuncSetAttribute(gemm01, cudaFuncAttributeMaxDynamicSharedMemorySize, SMG);
    cudaFuncSetAttribute(node1, cudaFuncAttributeMaxDynamicSharedMemorySize, SMN);

    kzero<<<(NN * 16 + NN / 2 + 255) / 256, 256>>>();
    k0<<<1, 256>>>(We0, Wfe0, Wfn0, We1, Wn1, Wfn1, bfe0);
    k1<<<(NN * 64 + 255) / 256, 256>>>(x, Wn0);

    // [P | Bn] = n1h @ Wcombh^T
    gemm01<<<dim3(MTILES, 4), 256, SMG>>>(NN);

    // persistent pipelined fused edge kernel
    edge_kernel<<<PBLOCKS, 256, SME>>>(ei, ea);

    // fused layer-1 node megakernel (BN0 + n1_1 GEMM + out GEMM + BN1)
    node1<<<MTILES, 256, SMN>>>(bfn0, g0, b0, rm0, rv0,
                                bfn1, g1, b1, rm1, rv1, (float*)d_out);
}

// round 17
// speedup vs baseline: 1.0312x; 1.0312x over previous
#include <cuda_runtime.h>
#include <cuda_fp16.h>
#include <cstdint>
#include <cstddef>

#define NN 50000
#define EE 1600000
#define MTILES ((NN + 63) / 64)   // 782
#define ETILES (EE / 128)         // 12500 (exact)
#define PBLOCKS 296               // 2 per SM

// ---------------- scratch (static device globals; no dynamic alloc) ----------
__device__ __align__(16) __half g_n1h[(size_t)NN * 64];
__device__ __align__(16) __half g_Ph[(size_t)NN * 128];
__device__ __align__(16) float  g_Bn[(size_t)NN * 128];
__device__ __align__(16) float  g_AGG[(size_t)NN * 64];
__device__ __align__(16) __half g_AGGh[(size_t)NN * 128];  // cols 0..63 agg1(fp16), 64..127 n1_1
__device__ __align__(16) __half g_x1h[(size_t)NN * 128];
__device__ __align__(16) float  g_ssum[2 * NN];            // interleaved {spos, sneg}
__device__ __align__(16) float g_cpos[128];
__device__ __align__(16) float g_cneg[128];
__device__ __align__(16) float g_apos[128];
__device__ __align__(16) float g_aneg[128];
__device__ float  g_wpos[64], g_wneg[64];
__device__ __align__(16) uint4 g_CB[64];
__device__ __align__(16) __half g_Wcombh[256 * 64];
__device__ __align__(16) __half g_We1h[64 * 128];
__device__ __align__(16) __half g_Wn1h[64 * 128];
__device__ __align__(16) __half g_Wfn1h[128 * 128];

// ---------------- helpers ----------------------------------------------------
__device__ __forceinline__ void red_add_v4(float* p, float4 v) {
    asm volatile("red.global.add.v4.f32 [%0], {%1,%2,%3,%4};"
                 :: "l"(p), "f"(v.x), "f"(v.y), "f"(v.z), "f"(v.w) : "memory");
}
__device__ __forceinline__ void red_add_v2(float* p, float2 v) {
    asm volatile("red.global.add.v2.f32 [%0], {%1,%2};"
                 :: "l"(p), "f"(v.x), "f"(v.y) : "memory");
}
__device__ __forceinline__ uint32_t smem_u32(const void* p) {
    uint32_t a;
    asm("{ .reg .u64 t; cvta.to.shared.u64 t, %1; cvt.u32.u64 %0, t; }" : "=r"(a) : "l"(p));
    return a;
}

// ---------------- K0: fold rank-1 edge path + fp16 weight conversions --------
__global__ void k0(const float* __restrict__ We0, const float* __restrict__ Wfe0,
                   const float* __restrict__ Wfn0, const float* __restrict__ We1,
                   const float* __restrict__ Wn1, const float* __restrict__ Wfn1,
                   const float* __restrict__ bfe0) {
    int t = threadIdx.x;
    if (t < 64) {
        float w = We0[t];
        g_wpos[t] = fmaxf(w, 0.f);
        g_wneg[t] = fminf(w, 0.f);
    }
    __syncthreads();
    if (t < 128) {
        float cp = 0.f, cn = 0.f, ap = 0.f, an = 0.f;
        for (int j = 0; j < 64; j++) {
            float wp = g_wpos[j], wn = g_wneg[j];
            float we = Wfe0[t * 128 + 64 + j];
            float wf = Wfn0[t * 128 + j];
            cp += wp * we; cn += wn * we;
            ap += wp * wf; an += wn * wf;
        }
        g_cpos[t] = cp; g_cneg[t] = cn; g_apos[t] = ap; g_aneg[t] = an;
    }
    __syncthreads();
    if (t < 64) {
        uint4 cb;
        __half2* h = (__half2*)&cb;
        h[0] = __floats2half2_rn(g_cpos[2 * t], g_cpos[2 * t + 1]);
        h[1] = __floats2half2_rn(g_cneg[2 * t], g_cneg[2 * t + 1]);
        h[2] = __floats2half2_rn(bfe0[2 * t], bfe0[2 * t + 1]);
        h[3] = __floats2half2_rn(0.f, 0.f);
        g_CB[t] = cb;
    }
    for (int idx = t; idx < 256 * 64; idx += blockDim.x) {
        int r = idx >> 6, j = idx & 63;
        float v = (r < 128) ? Wfe0[r * 128 + j] : Wfn0[(r - 128) * 128 + 64 + j];
        g_Wcombh[idx] = __float2half(v);
    }
    for (int idx = t; idx < 64 * 128; idx += blockDim.x) {
        g_We1h[idx] = __float2half(We1[idx]);
        g_Wn1h[idx] = __float2half(Wn1[idx]);
    }
    for (int idx = t; idx < 128 * 128; idx += blockDim.x)
        g_Wfn1h[idx] = __float2half(Wfn1[idx]);
}

// ---------------- K1: n1h = relu(x @ Wn0^T) fp16 ------------------------------
__global__ void k1(const float* __restrict__ x, const float* __restrict__ Wn0) {
    int t = blockIdx.x * blockDim.x + threadIdx.x;
    if (t >= NN * 64) return;
    int n = t >> 6, j = t & 63;
    const float* xr = x + (size_t)n * 16;
    const float* wr = Wn0 + j * 16;
    float s = 0.f;
#pragma unroll
    for (int k = 0; k < 16; k++) s += xr[k] * __ldg(wr + k);
    g_n1h[t] = __float2half(fmaxf(s, 0.f));
}

// ---------------- gemm01: HMMA [M,64] @ Wcombh[256,64]^T ----------------------
// Also zeroes g_AGG/g_ssum for its node tile (blockIdx.y==3 slice) so the
// standalone kzero launch is eliminated.
__global__ __launch_bounds__(256) void gemm01(int M) {
    extern __shared__ char smc[];
    const uint32_t uA = smem_u32(smc);
    const uint32_t uB = uA + 8192;
    int t = threadIdx.x;
    int m0 = blockIdx.x * 64;
    const __half* Bt = g_Wcombh + (size_t)(blockIdx.y * 64) * 64;

    if (blockIdx.y == 3) {
        float4 z = make_float4(0.f, 0.f, 0.f, 0.f);
#pragma unroll
        for (int ii = 0; ii < 4; ii++) {
            int idx = t + (ii << 8);          // 0..1023
            int row = idx >> 4, c4 = (idx & 15) << 2;
            int m = m0 + row;
            if (m < NN) *(float4*)(g_AGG + (size_t)m * 64 + c4) = z;
        }
        if (t < 32 && (2 * m0 + t * 4 + 3) < 2 * NN)
            ((float4*)(g_ssum + 2 * m0))[t] = z;
    }

#pragma unroll
    for (int ii = 0; ii < 2; ii++) {
        int seg = t + (ii << 8);
        int row = seg >> 3, cs = seg & 7;
        uint4 v = make_uint4(0, 0, 0, 0);
        if (m0 + row < M) v = *((const uint4*)(g_n1h + (size_t)(m0 + row) * 64) + cs);
        int cb = (cs << 4) ^ ((row & 7) << 4);
        *(uint4*)(smc + row * 128 + cb) = v;
    }
#pragma unroll
    for (int ii = 0; ii < 2; ii++) {
        int seg = t + (ii << 8);
        int row = seg >> 3, cs = seg & 7;
        uint4 v = *((const uint4*)(Bt + row * 64) + cs);
        int cb = (cs << 4) ^ ((row & 7) << 4);
        *(uint4*)(smc + 8192 + row * 128 + cb) = v;
    }
    __syncthreads();

    int lane = t & 31, w = t >> 5;
    int mw = (w & 3) << 4;
    int nw = w >> 2;
    int selA = lane >> 3, rA = lane & 7;
    int arow = mw + rA + ((selA & 1) << 3);
    int acb0 = (selA >> 1) << 4;
    int ax = (arow & 7) << 4;
    uint32_t aRowBase = uA + arow * 128;
    int selB = (lane >> 3) & 1, rB = lane & 7;
    int bx = rB << 4;

    float acc[4][4];
#pragma unroll
    for (int j = 0; j < 4; j++)
#pragma unroll
        for (int i = 0; i < 4; i++) acc[j][i] = 0.f;

#pragma unroll
    for (int k = 0; k < 4; k++) {
        uint32_t a0, a1, a2, a3;
        uint32_t aAddr = aRowBase + (((k << 5) + acb0) ^ ax);
        asm volatile("ldmatrix.sync.aligned.m8n8.x4.shared.b16 {%0,%1,%2,%3}, [%4];"
                     : "=r"(a0), "=r"(a1), "=r"(a2), "=r"(a3) : "r"(aAddr));
#pragma unroll
        for (int j = 0; j < 4; j++) {
            int brow = (nw << 5) + (j << 3) + rB;
            uint32_t bAddr = uB + brow * 128 + (((k << 5) + (selB << 4)) ^ bx);
            uint32_t b0, b1;
            asm volatile("ldmatrix.sync.aligned.m8n8.x2.shared.b16 {%0,%1}, [%2];"
                         : "=r"(b0), "=r"(b1) : "r"(bAddr));
            asm volatile("mma.sync.aligned.m16n8k16.row.col.f32.f16.f16.f32 "
                         "{%0,%1,%2,%3}, {%4,%5,%6,%7}, {%8,%9}, {%0,%1,%2,%3};"
                         : "+f"(acc[j][0]), "+f"(acc[j][1]), "+f"(acc[j][2]), "+f"(acc[j][3])
                         : "r"(a0), "r"(a1), "r"(a2), "r"(a3), "r"(b0), "r"(b1));
        }
    }

    int col = (nw << 5) + ((lane & 3) << 1);
    int row0 = mw + (lane >> 2);
    int gcol = blockIdx.y * 64;
#pragma unroll
    for (int j = 0; j < 4; j++) {
        int c = col + (j << 3);
#pragma unroll
        for (int h = 0; h < 2; h++) {
            int m = m0 + row0 + h * 8;
            if (m >= M) continue;
            float v0 = acc[j][h * 2], v1 = acc[j][h * 2 + 1];
            if (gcol < 128) {
                *(__half2*)(g_Ph + (size_t)m * 128 + gcol + c) = __floats2half2_rn(v0, v1);
            } else {
                *(float2*)(g_Bn + (size_t)m * 128 + (gcol - 128) + c) = make_float2(v0, v1);
            }
        }
    }
}

// ---------------- persistent pipelined edge kernel ----------------------------
struct EdgeRegs {
    uint4 vs1[4], vd1[4], vs2[4], vd2[4];
    int dst1, dst2;
    float a1, a2;
};

__device__ __forceinline__ void fetch_tile(
    int tile, int erow, int q, const int* __restrict__ ei,
    const float* __restrict__ ea, EdgeRegs& r, int* sDstBuf) {
    int e0 = tile << 7;
    int e1i = e0 + erow;
    int e2i = e0 + erow + 64;
    int src1 = ei[e1i]; r.dst1 = ei[EE + e1i]; r.a1 = ea[e1i];
    int src2 = ei[e2i]; r.dst2 = ei[EE + e2i]; r.a2 = ea[e2i];
    const uint4* Ps1 = (const uint4*)(g_Ph + (size_t)src1 * 128);
    const uint4* Pd1 = (const uint4*)(g_Ph + (size_t)r.dst1 * 128);
    const uint4* Ps2 = (const uint4*)(g_Ph + (size_t)src2 * 128);
    const uint4* Pd2 = (const uint4*)(g_Ph + (size_t)r.dst2 * 128);
#pragma unroll
    for (int s = 0; s < 4; s++) {
        int seg = s * 4 + q;
        r.vs1[s] = __ldg(Ps1 + seg);
        r.vd1[s] = __ldg(Pd1 + seg);
        r.vs2[s] = __ldg(Ps2 + seg);
        r.vd2[s] = __ldg(Pd2 + seg);
    }
    if (q == 0) {
        sDstBuf[erow] = r.dst1;
        sDstBuf[erow + 64] = r.dst2;
        red_add_v2(g_ssum + 2 * r.dst1, make_float2(fmaxf(r.a1, 0.f), fminf(r.a1, 0.f)));
        red_add_v2(g_ssum + 2 * r.dst2, make_float2(fmaxf(r.a2, 0.f), fminf(r.a2, 0.f)));
    }
}

__device__ __forceinline__ void build_tile(
    const EdgeRegs& r, int erow, int q, char* smc, uint32_t bufOff,
    const uint4* sCB) {
    const __half2 z2 = __floats2half2_rn(0.f, 0.f);
    const int erow2 = erow + 64;
    const int xr1 = (erow & 7) << 4;
    const int xr2 = (erow2 & 7) << 4;
    __half2 ap1 = __float2half2_rn(fmaxf(r.a1, 0.f));
    __half2 an1 = __float2half2_rn(fminf(r.a1, 0.f));
    __half2 ap2 = __float2half2_rn(fmaxf(r.a2, 0.f));
    __half2 an2 = __float2half2_rn(fminf(r.a2, 0.f));
#pragma unroll
    for (int s = 0; s < 4; s++) {
        int hc = (s << 5) + (q << 3);
        uint4 cbv[4];
#pragma unroll
        for (int p = 0; p < 4; p++) cbv[p] = sCB[(hc >> 1) + p];

        const __half2* hs1 = (const __half2*)&r.vs1[s];
        const __half2* hd1 = (const __half2*)&r.vd1[s];
        const __half2* hs2 = (const __half2*)&r.vs2[s];
        const __half2* hd2 = (const __half2*)&r.vd2[s];
        uint4 out1, out2;
        __half2* ho1 = (__half2*)&out1;
        __half2* ho2 = (__half2*)&out2;
#pragma unroll
        for (int p = 0; p < 4; p++) {
            const __half2* hcb = (const __half2*)&cbv[p];
            __half2 t1 = __hfma2(ap1, hcb[0], __hfma2(an1, hcb[1], hcb[2]));
            __half2 t2 = __hfma2(ap2, hcb[0], __hfma2(an2, hcb[1], hcb[2]));
            ho1[p] = __hmax2(__hadd2(__hadd2(hs1[p], hd1[p]), t1), z2);
            ho2[p] = __hmax2(__hadd2(__hadd2(hs2[p], hd2[p]), t2), z2);
        }
        *(uint4*)(smc + bufOff + erow * 256 + ((hc << 1) ^ xr1)) = out1;
        *(uint4*)(smc + bufOff + erow2 * 256 + ((hc << 1) ^ xr2)) = out2;
    }
}

__global__ __launch_bounds__(256, 2) void edge_kernel(
    const int* __restrict__ ei, const float* __restrict__ ea) {
    extern __shared__ char smc[];
    // U0 [0,32768), U1 [32768,65536), W [65536,81920)
    __shared__ int   sDst[2][128];
    __shared__ uint4 sCB[64];

    const uint32_t uU = smem_u32(smc);
    const uint32_t uW = uU + 65536;

    int t = threadIdx.x;
    const int erow = t >> 2;
    const int q = t & 3;

    if (t < 64) sCB[t] = g_CB[t];
#pragma unroll
    for (int ii = 0; ii < 4; ii++) {
        int seg = t + (ii << 8);
        int row = seg >> 4, cs = seg & 15;
        uint4 v = *((const uint4*)(g_We1h + row * 128) + cs);
        int cb = (cs << 4) ^ ((row & 7) << 4);
        *(uint4*)(smc + 65536 + row * 256 + cb) = v;
    }

    int lane = t & 31, w = t >> 5;
    int mw = (w & 3) << 5;
    int nw = w >> 2;
    int selA = lane >> 3, rA = lane & 7;
    int acb0 = (selA >> 1) << 4;
    int rowOff = rA + ((selA & 1) << 3);
    int selB = (lane >> 3) & 1, rB = lane & 7;
    int bx = rB << 4;
    int qe = lane & 3, qodd = qe & 1;
    int colb = (nw << 5) + ((qe >> 1) << 2);

    int tile = blockIdx.x;
    EdgeRegs reg;
    fetch_tile(tile, erow, q, ei, ea, reg, sDst[0]);
    __syncthreads();
    build_tile(reg, erow, q, smc, 0, sCB);
    __syncthreads();

    int buf = 0;
    while (true) {
        int next = tile + PBLOCKS;
        bool have_next = (next < ETILES);
        if (have_next)
            fetch_tile(next, erow, q, ei, ea, reg, sDst[buf ^ 1]);

        uint32_t uBuf = uU + ((uint32_t)buf << 15);
        float acc[2][4][4];
#pragma unroll
        for (int mi = 0; mi < 2; mi++)
#pragma unroll
            for (int j = 0; j < 4; j++)
#pragma unroll
                for (int i = 0; i < 4; i++) acc[mi][j][i] = 0.f;

#pragma unroll
        for (int k = 0; k < 8; k++) {
            uint32_t a[2][4];
#pragma unroll
            for (int mi = 0; mi < 2; mi++) {
                int arow = mw + (mi << 4) + rowOff;
                uint32_t aAddr = uBuf + arow * 256 + (((k << 5) + acb0) ^ ((arow & 7) << 4));
                asm volatile("ldmatrix.sync.aligned.m8n8.x4.shared.b16 {%0,%1,%2,%3}, [%4];"
                             : "=r"(a[mi][0]), "=r"(a[mi][1]), "=r"(a[mi][2]), "=r"(a[mi][3])
                             : "r"(aAddr));
            }
#pragma unroll
            for (int j = 0; j < 4; j++) {
                int brow = (nw << 5) + (j << 3) + rB;
                uint32_t bAddr = uW + brow * 256 + (((k << 5) + (selB << 4)) ^ bx);
                uint32_t b0, b1;
                asm volatile("ldmatrix.sync.aligned.m8n8.x2.shared.b16 {%0,%1}, [%2];"
                             : "=r"(b0), "=r"(b1) : "r"(bAddr));
#pragma unroll
                for (int mi = 0; mi < 2; mi++) {
                    asm volatile("mma.sync.aligned.m16n8k16.row.col.f32.f16.f16.f32 "
                                 "{%0,%1,%2,%3}, {%4,%5,%6,%7}, {%8,%9}, {%0,%1,%2,%3};"
                                 : "+f"(acc[mi][j][0]), "+f"(acc[mi][j][1]),
                                   "+f"(acc[mi][j][2]), "+f"(acc[mi][j][3])
                                 : "r"(a[mi][0]), "r"(a[mi][1]), "r"(a[mi][2]), "r"(a[mi][3]),
                                   "r"(b0), "r"(b1));
                }
            }
        }

#pragma unroll
        for (int mi = 0; mi < 2; mi++) {
            int row0 = mw + (mi << 4) + (lane >> 2);
#pragma unroll
            for (int j = 0; j < 4; j++)
#pragma unroll
                for (int c = 0; c < 4; c++) acc[mi][j][c] = fmaxf(acc[mi][j][c], 0.f);
#pragma unroll
            for (int j = 0; j < 4; j++) {
                float s0 = __shfl_xor_sync(0xffffffffu,
                                           qodd ? acc[mi][j][0] : acc[mi][j][2], 1);
                float s1 = __shfl_xor_sync(0xffffffffu,
                                           qodd ? acc[mi][j][1] : acc[mi][j][3], 1);
                int row = qodd ? (row0 + 8) : row0;
                int d = sDst[buf][row];
                float4 v = qodd ? make_float4(s0, s1, acc[mi][j][2], acc[mi][j][3])
                                : make_float4(acc[mi][j][0], acc[mi][j][1], s0, s1);
                red_add_v4(g_AGG + (size_t)d * 64 + colb + (j << 3), v);
            }
        }

        if (!have_next) break;
        build_tile(reg, erow, q, smc, (uint32_t)(buf ^ 1) << 15, sCB);
        __syncthreads();
        buf ^= 1;
        tile = next;
    }
}

// ---------------- K4a (vectorized, 4 cols/thread) -----------------------------
__global__ void k4a(const float* __restrict__ bfn0, const float* __restrict__ g0,
                    const float* __restrict__ b0, const float* __restrict__ rm0,
                    const float* __restrict__ rv0) {
    int t = blockIdx.x * blockDim.x + threadIdx.x;
    if (t >= NN * 32) return;
    int n = t >> 5, c4 = (t & 31) << 2;
    float sp = g_ssum[2 * n], sn = g_ssum[2 * n + 1];
    float4 bn = *(const float4*)(g_Bn + (size_t)n * 128 + c4);
    float4 ap = *(const float4*)(g_apos + c4);
    float4 an = *(const float4*)(g_aneg + c4);
    float4 bf = *(const float4*)(bfn0 + c4);
    float4 rm = *(const float4*)(rm0 + c4);
    float4 rv = *(const float4*)(rv0 + c4);
    float4 gg = *(const float4*)(g0 + c4);
    float4 bb = *(const float4*)(b0 + c4);
    float v0 = fmaxf(sp * ap.x + sn * an.x + bn.x + bf.x, 0.f);
    float v1 = fmaxf(sp * ap.y + sn * an.y + bn.y + bf.y, 0.f);
    float v2 = fmaxf(sp * ap.z + sn * an.z + bn.z + bf.z, 0.f);
    float v3 = fmaxf(sp * ap.w + sn * an.w + bn.w + bf.w, 0.f);
    v0 = (v0 - rm.x) * rsqrtf(rv.x + 1e-5f) * gg.x + bb.x;
    v1 = (v1 - rm.y) * rsqrtf(rv.y + 1e-5f) * gg.y + bb.y;
    v2 = (v2 - rm.z) * rsqrtf(rv.z + 1e-5f) * gg.z + bb.z;
    v3 = (v3 - rm.w) * rsqrtf(rv.w + 1e-5f) * gg.w + bb.w;
    uint2 out;
    ((__half2*)&out)[0] = __floats2half2_rn(v0, v1);
    ((__half2*)&out)[1] = __floats2half2_rn(v2, v3);
    *(uint2*)(g_x1h + (size_t)n * 128 + c4) = out;
    if (c4 < 64) {
        float4 ag = *(const float4*)(g_AGG + (size_t)n * 64 + c4);
        uint2 oh;
        ((__half2*)&oh)[0] = __floats2half2_rn(ag.x, ag.y);
        ((__half2*)&oh)[1] = __floats2half2_rn(ag.z, ag.w);
        *(uint2*)(g_AGGh + (size_t)n * 128 + c4) = oh;
    }
}

// ---------------- HMMA node GEMM: C = epi(Ah[M,128] @ Bh[64,128]^T) -----------
template <int MODE>
__global__ __launch_bounds__(256) void hgemm(
    const __half* __restrict__ A, int M, const __half* __restrict__ B,
    void* __restrict__ Cv, int cbase,
    const float* __restrict__ bias, const float* __restrict__ bng,
    const float* __restrict__ bnb, const float* __restrict__ bnm,
    const float* __restrict__ bnv) {
    extern __shared__ char smc[];
    const uint32_t uU = smem_u32(smc);
    const uint32_t uW = uU + 16384;
    int t = threadIdx.x;
    int m0 = blockIdx.x * 64;
    const __half* Bt = B + (size_t)(blockIdx.y * 64) * 128;

#pragma unroll
    for (int ii = 0; ii < 4; ii++) {
        int seg = t + (ii << 8);
        int row = seg >> 4, cs = seg & 15;
        uint4 v = make_uint4(0, 0, 0, 0);
        if (m0 + row < M) v = *((const uint4*)(A + (size_t)(m0 + row) * 128) + cs);
        int cb = (cs << 4) ^ ((row & 7) << 4);
        *(uint4*)(smc + row * 256 + cb) = v;
    }
#pragma unroll
    for (int ii = 0; ii < 4; ii++) {
        int seg = t + (ii << 8);
        int row = seg >> 4, cs = seg & 15;
        uint4 v = *((const uint4*)(Bt + row * 128) + cs);
        int cb = (cs << 4) ^ ((row & 7) << 4);
        *(uint4*)(smc + 16384 + row * 256 + cb) = v;
    }
    __syncthreads();

    int lane = t & 31, w = t >> 5;
    int mw = (w & 3) << 4;
    int nw = w >> 2;
    int selA = lane >> 3, rA = lane & 7;
    int arow = mw + rA + ((selA & 1) << 3);
    int acb0 = (selA >> 1) << 4;
    int ax = (arow & 7) << 4;
    uint32_t aRowBase = uU + arow * 256;
    int selB = (lane >> 3) & 1, rB = lane & 7;
    int bx = rB << 4;

    float acc[4][4];
#pragma unroll
    for (int j = 0; j < 4; j++)
#pragma unroll
        for (int i = 0; i < 4; i++) acc[j][i] = 0.f;

#pragma unroll
    for (int k = 0; k < 8; k++) {
        uint32_t a0, a1, a2, a3;
        uint32_t aAddr = aRowBase + (((k << 5) + acb0) ^ ax);
        asm volatile("ldmatrix.sync.aligned.m8n8.x4.shared.b16 {%0,%1,%2,%3}, [%4];"
                     : "=r"(a0), "=r"(a1), "=r"(a2), "=r"(a3) : "r"(aAddr));
#pragma unroll
        for (int j = 0; j < 4; j++) {
            int brow = (nw << 5) + (j << 3) + rB;
            uint32_t bAddr = uW + brow * 256 + (((k << 5) + (selB << 4)) ^ bx);
            uint32_t b0, b1;
            asm volatile("ldmatrix.sync.aligned.m8n8.x2.shared.b16 {%0,%1}, [%2];"
                         : "=r"(b0), "=r"(b1) : "r"(bAddr));
            asm volatile("mma.sync.aligned.m16n8k16.row.col.f32.f16.f16.f32 "
                         "{%0,%1,%2,%3}, {%4,%5,%6,%7}, {%8,%9}, {%0,%1,%2,%3};"
                         : "+f"(acc[j][0]), "+f"(acc[j][1]), "+f"(acc[j][2]), "+f"(acc[j][3])
                         : "r"(a0), "r"(a1), "r"(a2), "r"(a3), "r"(b0), "r"(b1));
        }
    }

    int col = (nw << 5) + ((lane & 3) << 1);
    int row0 = mw + (lane >> 2);
#pragma unroll
    for (int j = 0; j < 4; j++) {
        int c = col + (j << 3);
        int gc = blockIdx.y * 64 + c;
#pragma unroll
        for (int h = 0; h < 2; h++) {
            int m = m0 + row0 + h * 8;
            if (m >= M) continue;
            float v0 = acc[j][h * 2], v1 = acc[j][h * 2 + 1];
            if (MODE == 1) {
                v0 = fmaxf(v0, 0.f); v1 = fmaxf(v1, 0.f);
                __half* C = (__half*)Cv;
                *(__half2*)(C + (size_t)m * 128 + cbase + gc) =
                    __floats2half2_rn(v0, v1);
            } else {
                v0 += bias[gc]; v1 += bias[gc + 1];
                v0 = fmaxf(v0, 0.f); v1 = fmaxf(v1, 0.f);
                v0 = (v0 - bnm[gc]) * rsqrtf(bnv[gc] + 1e-5f) * bng[gc] + bnb[gc];
                v1 = (v1 - bnm[gc + 1]) * rsqrtf(bnv[gc + 1] + 1e-5f) * bng[gc + 1] + bnb[gc + 1];
                float* C = (float*)Cv;
                *(float2*)(C + (size_t)m * 128 + gc) = make_float2(v0, v1);
            }
        }
    }
}

// ---------------- host launcher ----------------------------------------------
extern "C" void kernel_launch(void* const* d_in, const int* in_sizes, int n_in,
                              void* d_out, int out_size) {
    const float* x    = (const float*)d_in[0];
    const float* ea   = (const float*)d_in[1];
    const int*   ei   = (const int*)d_in[2];
    const float* Wn0  = (const float*)d_in[3];
    const float* We0  = (const float*)d_in[4];
    const float* Wfn0 = (const float*)d_in[5];
    const float* bfn0 = (const float*)d_in[6];
    const float* Wfe0 = (const float*)d_in[7];
    const float* bfe0 = (const float*)d_in[8];
    const float* g0   = (const float*)d_in[9];
    const float* b0   = (const float*)d_in[10];
    const float* rm0  = (const float*)d_in[11];
    const float* rv0  = (const float*)d_in[12];
    const float* Wn1  = (const float*)d_in[13];
    const float* We1  = (const float*)d_in[14];
    const float* Wfn1 = (const float*)d_in[15];
    const float* bfn1 = (const float*)d_in[16];
    const float* g1   = (const float*)d_in[19];
    const float* b1   = (const float*)d_in[20];
    const float* rm1  = (const float*)d_in[21];
    const float* rv1  = (const float*)d_in[22];

    __half *p_x1h, *p_AGGh, *p_Wn1h, *p_Wfn1h;
    cudaGetSymbolAddress((void**)&p_x1h, g_x1h);
    cudaGetSymbolAddress((void**)&p_AGGh, g_AGGh);
    cudaGetSymbolAddress((void**)&p_Wn1h, g_Wn1h);
    cudaGetSymbolAddress((void**)&p_Wfn1h, g_Wfn1h);

    const int SMG = 16384;   // gemm01
    const int SME = 81920;   // edge kernel
    const int SMH = 32768;   // hgemm
    cudaFuncSetAttribute(edge_kernel, cudaFuncAttributeMaxDynamicSharedMemorySize, SME);
    cudaFuncSetAttribute(gemm01, cudaFuncAttributeMaxDynamicSharedMemorySize, SMG);
    cudaFuncSetAttribute(hgemm<1>, cudaFuncAttributeMaxDynamicSharedMemorySize, SMH);
    cudaFuncSetAttribute(hgemm<2>, cudaFuncAttributeMaxDynamicSharedMemorySize, SMH);

    k0<<<1, 256>>>(We0, Wfe0, Wfn0, We1, Wn1, Wfn1, bfe0);
    k1<<<(NN * 64 + 255) / 256, 256>>>(x, Wn0);

    // [P | Bn] = n1h @ Wcombh^T ; y==3 slice also zeroes g_AGG/g_ssum
    gemm01<<<dim3(MTILES, 4), 256, SMG>>>(NN);

    // persistent pipelined fused edge kernel
    edge_kernel<<<PBLOCKS, 256, SME>>>(ei, ea);

    // x1h = BN0(relu(agg0-part + Bn + bfn0)); agg1 -> fp16
    k4a<<<(NN * 32 + 255) / 256, 256>>>(bfn0, g0, b0, rm0, rv0);

    // n1_1 = relu(x1h @ Wn1h^T) -> AGGh cols 64..127 (fp16)
    hgemm<1><<<dim3(MTILES, 1), 256, SMH>>>(
        p_x1h, NN, p_Wn1h, p_AGGh, 64,
        nullptr, nullptr, nullptr, nullptr, nullptr);

    // out = BN1(relu([agg1 | n1_1] @ Wfn1^T + bfn1))
    hgemm<2><<<dim3(MTILES, 2), 256, SMH>>>(
        p_AGGh, NN, p_Wfn1h, d_out, 0, bfn1, g1, b1, rm1, rv1);
}